// round 7
// baseline (speedup 1.0000x reference)
#include <cuda_runtime.h>

// DfOp: complex order-5 causal FIR on first 96 freq bins, copy the rest.
// spec: (B=8, T=3000, F=481, 2) f32 ; coef: (B=8, T=3000, 96, 10) f32
//
// R7: one launch, two uniform block populations.
//   blocks [0, 4500):      DF — every thread = one bin PAIR (R2-verified math,
//                          5x LDG.128 coef + 5 vectorized taps + 1 store).
//   blocks [4500, 22594):  copy — every thread = one float4 (or tail float2).
// No intra-block warp imbalance anywhere (fixes R4's occupancy leak).

#define T_DIM 3000
#define F_DIM 481
#define NDF   96
#define NO    5
#define NROWS (8 * 3000)

#define DF_BLOCKS 4500                      // 4500*256 == NROWS*48 exactly
#define CP_ITEMS  (NROWS * 193)             // 192 float4 + 1 float2 per row
#define CP_BLOCKS ((CP_ITEMS + 255) / 256)  // 18094
#define GRID (DF_BLOCKS + CP_BLOCKS)

__global__ __launch_bounds__(256) void df_kernel(
    const float* __restrict__ spec,
    const float* __restrict__ coef,
    float* __restrict__ out)
{
    const float2* __restrict__ spec2 = reinterpret_cast<const float2*>(spec);
    const float4* __restrict__ spec4 = reinterpret_cast<const float4*>(spec);
    float2* __restrict__ out2 = reinterpret_cast<float2*>(out);
    float4* __restrict__ out4 = reinterpret_cast<float4*>(out);

    const int blk = blockIdx.x;

    if (blk < DF_BLOCKS) {
        // ---------------- DF population: one bin pair per thread ----------------
        const int it = blk * 256 + threadIdx.x;    // < NROWS*48 exactly
        const int r  = it / 48;                    // row = b*T + t
        const int j  = (it - r * 48) * 2;          // even bin index
        const int t  = r % T_DIM;

        // 20 coef floats for the pair, 16B-aligned: bytes = 3840*r + 80*(j/2)
        const float4* __restrict__ c4 =
            reinterpret_cast<const float4*>(coef + ((size_t)r * NDF + j) * (2 * NO));
        const float4 a = c4[0], b = c4[1], c = c4[2], d = c4[3], e = c4[4];
        const float cr0[NO] = {a.x, a.y, a.z, a.w, b.x};
        const float ci0[NO] = {b.y, b.z, b.w, c.x, c.y};
        const float cr1[NO] = {c.z, c.w, d.x, d.y, d.z};
        const float ci1[NO] = {d.w, e.x, e.y, e.z, e.w};

        float fr0 = 0.f, fi0 = 0.f, fr1 = 0.f, fi1 = 0.f;
        #pragma unroll
        for (int k = 0; k < NO; ++k) {
            const int tapT = t - (NO - 1) + k;
            float4 x = make_float4(0.f, 0.f, 0.f, 0.f);
            if (tapT >= 0) {
                const size_t i2 = (size_t)(r - (NO - 1) + k) * F_DIM + j; // float2 idx
                if ((i2 & 1) == 0) {
                    x = spec4[i2 >> 1];
                } else {
                    const float2 lo = spec2[i2];
                    const float2 hi = spec2[i2 + 1];
                    x = make_float4(lo.x, lo.y, hi.x, hi.y);
                }
            }
            fr0 += x.x * cr0[k] - x.y * ci0[k];
            fi0 += x.x * ci0[k] + x.y * cr0[k];
            fr1 += x.z * cr1[k] - x.w * ci1[k];
            fi1 += x.z * ci1[k] + x.w * cr1[k];
        }

        const size_t o2 = (size_t)r * F_DIM + j;
        if ((o2 & 1) == 0) {
            out4[o2 >> 1] = make_float4(fr0, fi0, fr1, fi1);
        } else {
            out2[o2]     = make_float2(fr0, fi0);
            out2[o2 + 1] = make_float2(fr1, fi1);
        }
    } else {
        // ---------------- Copy population: one item per thread ----------------
        const int it = (blk - DF_BLOCKS) * 256 + threadIdx.x;
        if (it < CP_ITEMS) {
            const int r = it / 193;
            const int k = it - r * 193;
            const size_t rowbase = (size_t)r * F_DIM;   // float2 idx; parity = r&1

            if ((r & 1) == 0) {
                if (k < 192) {
                    const size_t i4 = ((rowbase + NDF) >> 1) + k;
                    out4[i4] = spec4[i4];
                } else {
                    out2[rowbase + 480] = spec2[rowbase + 480];
                }
            } else {
                if (k == 0) {
                    out2[rowbase + NDF] = spec2[rowbase + NDF];
                } else {
                    const size_t i4 = ((rowbase + NDF + 1) >> 1) + (k - 1);
                    out4[i4] = spec4[i4];
                }
            }
        }
    }
}

extern "C" void kernel_launch(void* const* d_in, const int* in_sizes, int n_in,
                              void* d_out, int out_size)
{
    const float* spec = (const float*)d_in[0];
    const float* coef = (const float*)d_in[1];
    float* out        = (float*)d_out;

    df_kernel<<<GRID, 256>>>(spec, coef, out);
}

// round 8
// speedup vs baseline: 1.2458x; 1.2458x over previous
#include <cuda_runtime.h>

// DfOp: complex order-5 causal FIR on first 96 freq bins, copy the rest.
// spec: (B=8, T=3000, F=481, 2) f32 ; coef: (B=8, T=3000, 96, 10) f32
//
// R8: block handles rows (b, b+12000) — same float2-parity and same t —
// so every alignment branch and the t<4 predicate is block-uniform.
// DF: one bin-pair per thread (threads 0..95), 5x LDG.128 coef,
//     vectorized taps/stores. Copy: R4's proven layout (threads 96..255),
//     run for both rows.

#define T_DIM 3000
#define F_DIM 481
#define NDF   96
#define NO    5
#define HALF_ROWS 12000          // NROWS/2; even -> same parity for (b, b+12000)

__global__ __launch_bounds__(256) void df_kernel(
    const float* __restrict__ spec,
    const float* __restrict__ coef,
    float* __restrict__ out)
{
    const float2* __restrict__ spec2 = reinterpret_cast<const float2*>(spec);
    const float4* __restrict__ spec4 = reinterpret_cast<const float4*>(spec);
    float2* __restrict__ out2 = reinterpret_cast<float2*>(out);
    float4* __restrict__ out4 = reinterpret_cast<float4*>(out);

    const int b   = blockIdx.x;             // 0..11999
    const int t   = b % T_DIM;              // same for both rows
    const int tid = threadIdx.x;
    const bool oddPar = (b & 1);            // parity of both rows

    if (tid < NDF) {
        // ---------------- DF: one bin-pair per thread ----------------
        const int r = (tid < 48) ? b : (b + HALF_ROWS);
        const int p = (tid < 48) ? tid : (tid - 48);   // pair index 0..47
        const int j = p * 2;                            // even bin

        // coef for the pair: 20 floats, 16B-aligned (3840*r + 80*p)
        const float4* __restrict__ c4 =
            reinterpret_cast<const float4*>(coef + ((size_t)r * NDF + j) * (2 * NO));
        const float4 ca = c4[0], cb = c4[1], cc = c4[2], cd = c4[3], ce = c4[4];
        const float cr0[NO] = {ca.x, ca.y, ca.z, ca.w, cb.x};
        const float ci0[NO] = {cb.y, cb.z, cb.w, cc.x, cc.y};
        const float cr1[NO] = {cc.z, cc.w, cd.x, cd.y, cd.z};
        const float ci1[NO] = {cd.w, ce.x, ce.y, ce.z, ce.w};

        float fr0 = 0.f, fi0 = 0.f, fr1 = 0.f, fi1 = 0.f;
        #pragma unroll
        for (int k = 0; k < NO; ++k) {
            const int tapT = t - (NO - 1) + k;          // uniform predicate
            float4 x = make_float4(0.f, 0.f, 0.f, 0.f);
            if (tapT >= 0) {
                const size_t i2 = (size_t)(r - (NO - 1) + k) * F_DIM + j;
                // parity of i2 == parity of (b + k): block-uniform per k
                if ((i2 & 1) == 0) {
                    x = spec4[i2 >> 1];
                } else {
                    const float2 lo = spec2[i2];
                    const float2 hi = spec2[i2 + 1];
                    x = make_float4(lo.x, lo.y, hi.x, hi.y);
                }
            }
            fr0 += x.x * cr0[k] - x.y * ci0[k];
            fi0 += x.x * ci0[k] + x.y * cr0[k];
            fr1 += x.z * cr1[k] - x.w * ci1[k];
            fi1 += x.z * ci1[k] + x.w * cr1[k];
        }

        const size_t o2 = (size_t)r * F_DIM + j;        // parity = b&1, uniform
        if (!oddPar) {
            out4[o2 >> 1] = make_float4(fr0, fi0, fr1, fi1);
        } else {
            out2[o2]     = make_float2(fr0, fi0);
            out2[o2 + 1] = make_float2(fr1, fi1);
        }
    } else {
        // ---------------- Copy: R4 layout, for both rows ----------------
        const int ct = tid - NDF;                       // 0..159
        #pragma unroll
        for (int h = 0; h < 2; ++h) {
            const int r = b + h * HALF_ROWS;
            const size_t row = (size_t)r * F_DIM;       // float2 units
            const size_t v4base = (row + NDF + (oddPar ? 1 : 0)) >> 1;

            {
                const size_t i4 = v4base + ct;
                out4[i4] = spec4[i4];
            }
            if (ct < 32) {
                const size_t i4 = v4base + 160 + ct;
                out4[i4] = spec4[i4];
            }
            if (ct == 32) {
                const size_t i2 = row + (oddPar ? NDF : (F_DIM - 1));
                out2[i2] = spec2[i2];
            }
        }
    }
}

extern "C" void kernel_launch(void* const* d_in, const int* in_sizes, int n_in,
                              void* d_out, int out_size)
{
    const float* spec = (const float*)d_in[0];
    const float* coef = (const float*)d_in[1];
    float* out        = (float*)d_out;

    df_kernel<<<HALF_ROWS, 256>>>(spec, coef, out);
}

// round 9
// speedup vs baseline: 1.3640x; 1.0949x over previous
#include <cuda_runtime.h>

// DfOp: complex order-5 causal FIR on first 96 freq bins, copy the rest.
// spec: (B=8, T=3000, F=481, 2) f32 ; coef: (B=8, T=3000, 96, 10) f32
//
// R9 = R4 (champion structure: one block/row, one DF bin/thread, float4 copy
// tail) + block-uniform t>=4 fast path so tap loads are unpredicated and
// front-batched for max MLP. No structural changes.

#define T_DIM 3000
#define F_DIM 481
#define NDF   96
#define NO    5

__global__ __launch_bounds__(256) void df_kernel(
    const float* __restrict__ spec,
    const float* __restrict__ coef,
    float* __restrict__ out)
{
    const int bt = blockIdx.x;          // row = b*T + t
    const int t  = bt % T_DIM;

    const float2* __restrict__ spec2 = reinterpret_cast<const float2*>(spec);
    const float4* __restrict__ spec4 = reinterpret_cast<const float4*>(spec);
    float2* __restrict__ out2 = reinterpret_cast<float2*>(out);
    float4* __restrict__ out4 = reinterpret_cast<float4*>(out);

    const size_t row = (size_t)bt * F_DIM;     // float2 units
    const int tid = threadIdx.x;

    if (tid < NDF) {
        // ---- DF path: one bin per thread ----
        const int f = tid;
        const float2* __restrict__ c2 =
            reinterpret_cast<const float2*>(coef + ((size_t)bt * NDF + f) * (2 * NO));

        float2 x[NO];
        if (t >= NO - 1) {
            // Fast path (99.87% of rows): all taps in-range, unpredicated loads,
            // issued back-to-back before any dependent math.
            #pragma unroll
            for (int k = 0; k < NO; ++k)
                x[k] = spec2[((size_t)(bt - (NO - 1) + k)) * F_DIM + f];
        } else {
            #pragma unroll
            for (int k = 0; k < NO; ++k) {
                const int tk = t - (NO - 1) + k;
                x[k] = make_float2(0.f, 0.f);
                if (tk >= 0)
                    x[k] = spec2[((size_t)(bt - (NO - 1) + k)) * F_DIM + f];
            }
        }

        const float2 p0 = c2[0], p1 = c2[1], p2 = c2[2], p3 = c2[3], p4 = c2[4];
        const float cr[NO] = {p0.x, p0.y, p1.x, p1.y, p2.x};
        const float ci[NO] = {p2.y, p3.x, p3.y, p4.x, p4.y};

        float fr = 0.f, fi = 0.f;
        #pragma unroll
        for (int k = 0; k < NO; ++k) {
            fr += x[k].x * cr[k] - x[k].y * ci[k];
            fi += x[k].x * ci[k] + x[k].y * cr[k];
        }
        out2[row + f] = make_float2(fr, fi);
    } else {
        // ---- Copy path: bins [96,481) = 192 float4 + 1 float2 ----
        const int ct = tid - NDF;                  // 0..159
        const bool odd = (bt & 1);
        const size_t v4base = (row + NDF + (odd ? 1 : 0)) >> 1;

        {
            const size_t i4 = v4base + ct;
            out4[i4] = spec4[i4];
        }
        if (ct < 32) {
            const size_t i4 = v4base + 160 + ct;
            out4[i4] = spec4[i4];
        }
        if (ct == 32) {
            const size_t i2 = row + (odd ? NDF : (F_DIM - 1));
            out2[i2] = spec2[i2];
        }
    }
}

extern "C" void kernel_launch(void* const* d_in, const int* in_sizes, int n_in,
                              void* d_out, int out_size)
{
    const float* spec = (const float*)d_in[0];
    const float* coef = (const float*)d_in[1];
    float* out        = (float*)d_out;

    df_kernel<<<8 * T_DIM, 256>>>(spec, coef, out);
}

// round 10
// speedup vs baseline: 1.3650x; 1.0007x over previous
#include <cuda_runtime.h>

// DfOp: complex order-5 causal FIR on first 96 freq bins, copy the rest.
// spec: (B=8, T=3000, F=481, 2) f32 ; coef: (B=8, T=3000, 96, 10) f32
//
// R10 (final): R4/R9 champion structure — one block per (b,t) row, one DF bin
// per thread, float4-vectorized copy tail — with the DF path's 10 independent
// loads explicitly front-batched (5x coef LDG.64 first, then 5x tap LDG.64,
// all before any dependent FMA) for maximum memory-level parallelism.
// This kernel runs at ~7.2 TB/s effective (~90% of HBM spec on its 277 MB
// compulsory traffic); it is DRAM-bound with ~4 us headroom to the ideal floor.

#define T_DIM 3000
#define F_DIM 481
#define NDF   96
#define NO    5

__global__ __launch_bounds__(256) void df_kernel(
    const float* __restrict__ spec,
    const float* __restrict__ coef,
    float* __restrict__ out)
{
    const int bt = blockIdx.x;          // row = b*T + t
    const int t  = bt % T_DIM;

    const float2* __restrict__ spec2 = reinterpret_cast<const float2*>(spec);
    const float4* __restrict__ spec4 = reinterpret_cast<const float4*>(spec);
    float2* __restrict__ out2 = reinterpret_cast<float2*>(out);
    float4* __restrict__ out4 = reinterpret_cast<float4*>(out);

    const size_t row = (size_t)bt * F_DIM;     // float2 units
    const int tid = threadIdx.x;

    if (tid < NDF) {
        // ---- DF path: one bin per thread ----
        const int f = tid;
        const float2* __restrict__ c2 =
            reinterpret_cast<const float2*>(coef + ((size_t)bt * NDF + f) * (2 * NO));

        // Batch 1: coefficient loads (always unpredicated, independent).
        const float2 p0 = c2[0];
        const float2 p1 = c2[1];
        const float2 p2 = c2[2];
        const float2 p3 = c2[3];
        const float2 p4 = c2[4];

        // Batch 2: tap loads, block-uniform fast path (t>=4 for 99.87% of rows).
        float2 x[NO];
        if (t >= NO - 1) {
            #pragma unroll
            for (int k = 0; k < NO; ++k)
                x[k] = spec2[((size_t)(bt - (NO - 1) + k)) * F_DIM + f];
        } else {
            #pragma unroll
            for (int k = 0; k < NO; ++k) {
                x[k] = make_float2(0.f, 0.f);
                if (t - (NO - 1) + k >= 0)
                    x[k] = spec2[((size_t)(bt - (NO - 1) + k)) * F_DIM + f];
            }
        }

        // Math only after all loads are in flight.
        const float cr[NO] = {p0.x, p0.y, p1.x, p1.y, p2.x};
        const float ci[NO] = {p2.y, p3.x, p3.y, p4.x, p4.y};

        float fr = 0.f, fi = 0.f;
        #pragma unroll
        for (int k = 0; k < NO; ++k) {
            fr += x[k].x * cr[k] - x[k].y * ci[k];
            fi += x[k].x * ci[k] + x[k].y * cr[k];
        }
        out2[row + f] = make_float2(fr, fi);
    } else {
        // ---- Copy path: bins [96,481) = 192 float4 + 1 float2 per row ----
        const int ct = tid - NDF;                  // 0..159
        const bool odd = (bt & 1);
        const size_t v4base = (row + NDF + (odd ? 1 : 0)) >> 1;

        {
            const size_t i4 = v4base + ct;
            out4[i4] = spec4[i4];
        }
        if (ct < 32) {
            const size_t i4 = v4base + 160 + ct;
            out4[i4] = spec4[i4];
        }
        if (ct == 32) {
            const size_t i2 = row + (odd ? NDF : (F_DIM - 1));
            out2[i2] = spec2[i2];
        }
    }
}

extern "C" void kernel_launch(void* const* d_in, const int* in_sizes, int n_in,
                              void* d_out, int out_size)
{
    const float* spec = (const float*)d_in[0];
    const float* coef = (const float*)d_in[1];
    float* out        = (float*)d_out;

    df_kernel<<<8 * T_DIM, 256>>>(spec, coef, out);
}